// round 11
// baseline (speedup 1.0000x reference)
#include <cuda_runtime.h>
#include <cuda_fp16.h>
#include <cstdint>
#include <math.h>

// ---------------- problem constants ----------------
#define BB   4
#define NQ   8000
#define CC   256
#define NHD  8
#define NLV  4
#define NPT  4
#define DH   32
#define S_TOT 19947

#define MV (BB * S_TOT)   // 79788
#define MQ (BB * NQ)      // 32000

// ---------------- scratch ----------------
__device__ float g_value[(size_t)MV * CC];
__device__ float g_qout [(size_t)MQ * 384];
__device__ __half g_v_hi [(size_t)MV * CC];
__device__ __half g_v_lo [(size_t)MV * CC];
__device__ __half g_q_hi [(size_t)MQ * CC];
__device__ __half g_q_lo [(size_t)MQ * CC];
__device__ __half g_s_hi [(size_t)MQ * CC];
__device__ __half g_s_lo [(size_t)MQ * CC];
__device__ __half g_w_hi [65536 + 98304 + 65536];
__device__ __half g_w_lo [65536 + 98304 + 65536];
__device__ float g_qb[384];

// ---------------- helpers ----------------
__device__ __forceinline__ uint32_t smem_u32(const void* p) {
    uint32_t a;
    asm("{ .reg .u64 t; cvta.to.shared.u64 t, %1; cvt.u32.u64 %0, t; }" : "=r"(a) : "l"(p));
    return a;
}
__device__ __forceinline__ void ldsm4(uint32_t* r, uint32_t addr) {
    asm volatile("ldmatrix.sync.aligned.m8n8.x4.shared.b16 {%0,%1,%2,%3}, [%4];"
        : "=r"(r[0]), "=r"(r[1]), "=r"(r[2]), "=r"(r[3]) : "r"(addr));
}
// fp16 inputs, fp32 accumulate
__device__ __forceinline__ void mma_f32acc(float* c, const uint32_t* a, const uint32_t* b) {
    asm volatile(
        "mma.sync.aligned.m16n8k16.row.col.f32.f16.f16.f32 "
        "{%0,%1,%2,%3}, {%4,%5,%6,%7}, {%8,%9}, {%0,%1,%2,%3};"
        : "+f"(c[0]), "+f"(c[1]), "+f"(c[2]), "+f"(c[3])
        : "r"(a[0]), "r"(a[1]), "r"(a[2]), "r"(a[3]), "r"(b[0]), "r"(b[1]));
}
// fp16 inputs, fp16 accumulate (2x rate hypothesis)
__device__ __forceinline__ void mma_f16acc(uint32_t* c, const uint32_t* a, const uint32_t* b) {
    asm volatile(
        "mma.sync.aligned.m16n8k16.row.col.f16.f16.f16.f16 "
        "{%0,%1}, {%2,%3,%4,%5}, {%6,%7}, {%0,%1};"
        : "+r"(c[0]), "+r"(c[1])
        : "r"(a[0]), "r"(a[1]), "r"(a[2]), "r"(a[3]), "r"(b[0]), "r"(b[1]));
}
__device__ __forceinline__ void cp_async16(uint32_t dst, const void* src, uint32_t sz) {
    asm volatile("cp.async.cg.shared.global [%0], [%1], 16, %2;"
        :: "r"(dst), "l"(src), "r"(sz) : "memory");
}
#define CP_COMMIT() asm volatile("cp.async.commit_group;" ::: "memory")
#define CP_WAIT(n)  asm volatile("cp.async.wait_group %0;" :: "n"(n) : "memory")

// ---------------- mega conversion kernel (fp32 -> fp16 hi/lo) ----------
#define NB_V  (MV / 4)
#define NB_Q  (MQ / 4)
#define NB_WV 64
#define NB_WO 64
#define NB_WA 32
#define NB_WU 64
#define NB_TOT (NB_V + NB_Q + NB_WV + NB_WO + NB_WA + NB_WU + 1)

struct ConvArgs {
    const float *vlv, *query, *w_val, *w_off, *w_attn, *w_out, *b_off, *b_attn;
};

__global__ void __launch_bounds__(256) convert_all_kernel(ConvArgs a)
{
    const int blk = blockIdx.x;
    const int tid = threadIdx.x;

    const float* src;
    uint2 *hi, *lo;
    int rel;

    if (blk < NB_V) {
        src = a.vlv; hi = (uint2*)g_v_hi; lo = (uint2*)g_v_lo; rel = blk;
    } else if (blk < NB_V + NB_Q) {
        src = a.query; hi = (uint2*)g_q_hi; lo = (uint2*)g_q_lo; rel = blk - NB_V;
    } else if (blk < NB_V + NB_Q + NB_WV) {
        src = a.w_val; hi = (uint2*)g_w_hi; lo = (uint2*)g_w_lo; rel = blk - (NB_V + NB_Q);
    } else if (blk < NB_V + NB_Q + NB_WV + NB_WO) {
        src = a.w_off; hi = (uint2*)(g_w_hi + 65536); lo = (uint2*)(g_w_lo + 65536);
        rel = blk - (NB_V + NB_Q + NB_WV);
    } else if (blk < NB_V + NB_Q + NB_WV + NB_WO + NB_WA) {
        src = a.w_attn; hi = (uint2*)(g_w_hi + 131072); lo = (uint2*)(g_w_lo + 131072);
        rel = blk - (NB_V + NB_Q + NB_WV + NB_WO);
    } else if (blk < NB_V + NB_Q + NB_WV + NB_WO + NB_WA + NB_WU) {
        src = a.w_out; hi = (uint2*)(g_w_hi + 163840); lo = (uint2*)(g_w_lo + 163840);
        rel = blk - (NB_V + NB_Q + NB_WV + NB_WO + NB_WA);
    } else {
        for (int i = tid; i < 384; i += 256)
            g_qb[i] = (i < 256) ? a.b_off[i] : a.b_attn[i - 256];
        return;
    }

    const int i = rel * 256 + tid;
    const float4 v = ((const float4*)src)[i];
    __half h0 = __float2half_rn(v.x), h1 = __float2half_rn(v.y);
    __half h2 = __float2half_rn(v.z), h3 = __float2half_rn(v.w);
    __half l0 = __float2half_rn(v.x - __half2float(h0));
    __half l1 = __float2half_rn(v.y - __half2float(h1));
    __half l2 = __float2half_rn(v.z - __half2float(h2));
    __half l3 = __float2half_rn(v.w - __half2float(h3));
    uint2 hp, lp;
    hp.x = (uint32_t)__half_as_ushort(h0) | ((uint32_t)__half_as_ushort(h1) << 16);
    hp.y = (uint32_t)__half_as_ushort(h2) | ((uint32_t)__half_as_ushort(h3) << 16);
    lp.x = (uint32_t)__half_as_ushort(l0) | ((uint32_t)__half_as_ushort(l1) << 16);
    lp.y = (uint32_t)__half_as_ushort(l2) | ((uint32_t)__half_as_ushort(l3) << 16);
    hi[i] = hp; lo[i] = lp;
}

// ============ HMMA GEMM: 256 thr, warp 64x32, fp16-accum corrections ============
// tile 128x128, K staged in 8 half-stages of 32. smem 64KB: Ahi|Alo|Bhi|Blo 16KB planes.
struct GemmSeg {
    const __half *Ahi, *Alo, *Bhi, *Blo;
    const float* bias;
    float* C;
    int M, N, ntiles, tilesPerRow;
};

__global__ void __launch_bounds__(256, 1) gemm_tc2_kernel(GemmSeg s0, GemmSeg s1)
{
    extern __shared__ char smraw[];
    char* sm = (char*)(((uintptr_t)smraw + 1023) & ~(uintptr_t)1023);
    const uint32_t su = smem_u32(sm);
    float* pbias = (float*)(sm + 65536);

    int t = blockIdx.x;
    const __half *Ahi, *Alo, *Bhi, *Blo;
    const float* bias;
    float* Cmat;
    int M, N, tpr;
    if (t < s0.ntiles) {
        Ahi = s0.Ahi; Alo = s0.Alo; Bhi = s0.Bhi; Blo = s0.Blo;
        bias = s0.bias; Cmat = s0.C; M = s0.M; N = s0.N; tpr = s0.tilesPerRow;
    } else {
        t -= s0.ntiles;
        Ahi = s1.Ahi; Alo = s1.Alo; Bhi = s1.Bhi; Blo = s1.Blo;
        bias = s1.bias; Cmat = s1.C; M = s1.M; N = s1.N; tpr = s1.tilesPerRow;
    }
    const int bm = (t / tpr) * 128;
    const int bn = (t % tpr) * 128;

    const int tid  = threadIdx.x;
    const int lane = tid & 31;
    const int warp = tid >> 5;
    const int wm = (warp >> 2) * 64;      // 2x4 warp layout: 64 rows x 32 cols
    const int wn = (warp & 3) * 32;

    if (tid < 128) pbias[tid] = bias[bn + tid];

    float    acc [4][4][4];               // hi*hi, fp32 accum
    uint32_t accc[4][4][2];               // hi*lo + lo*hi, fp16 accum (shared)
#pragma unroll
    for (int i = 0; i < 4; i++)
#pragma unroll
        for (int j = 0; j < 4; j++) {
#pragma unroll
            for (int k = 0; k < 4; k++) acc[i][j][k] = 0.f;
            accc[i][j][0] = 0u; accc[i][j][1] = 0u;
        }

    const uint32_t mx = (uint32_t)((lane & 7) << 4);
    uint32_t aRow[4], bRow[2];
#pragma unroll
    for (int mi = 0; mi < 4; mi++)
        aRow[mi] = (uint32_t)((wm + mi * 16 + (lane & 15)) * 128);
    const uint32_t colA = (uint32_t)((lane >> 4) * 16);
#pragma unroll
    for (int nj2 = 0; nj2 < 2; nj2++)
        bRow[nj2] = (uint32_t)((wn + nj2 * 16 + (lane & 7) + ((lane >> 4) & 1) * 8) * 128);
    const uint32_t colB = (uint32_t)(((lane >> 3) & 1) * 16);

    auto load_half = [&](int hs) {
        const int hb = (hs & 1) * 64;
        const int ksrc = hs * 64;
#pragma unroll
        for (int pl = 0; pl < 4; pl++) {
            const __half* gsrc = (pl == 0) ? Ahi : (pl == 1) ? Alo : (pl == 2) ? Bhi : Blo;
            const bool isA = (pl < 2);
            const uint32_t pbase = su + (uint32_t)pl * 16384u;
#pragma unroll
            for (int it = 0; it < 2; it++) {
                const int idx = it * 256 + tid;
                const int r = idx >> 2;
                const int c = idx & 3;
                const uint32_t doff = (uint32_t)(r * 128)
                    + (uint32_t)((hb + c * 16) ^ ((r & 7) << 4));
                const int grow = (isA ? bm : bn) + r;
                const uint32_t sz = (isA && grow >= M) ? 0u : 16u;
                const size_t soff = (size_t)grow * 512 + ksrc + c * 16;
                cp_async16(pbase + doff, (const char*)gsrc + soff, sz);
            }
        }
    };

    load_half(0); CP_COMMIT();
    load_half(1); CP_COMMIT();

    for (int hs = 0; hs < 8; hs++) {
        if (hs < 7) CP_WAIT(1); else CP_WAIT(0);
        __syncthreads();

        const uint32_t hb = (uint32_t)((hs & 1) * 64);
#pragma unroll
        for (int kk = 0; kk < 2; kk++) {
            uint32_t ah[4][4], al[4][4], bh[2][4], bl[2][4];
            const uint32_t ca = (hb + (uint32_t)(kk * 32) + colA) ^ mx;
            const uint32_t cb = (hb + (uint32_t)(kk * 32) + colB) ^ mx;
#pragma unroll
            for (int mi = 0; mi < 4; mi++) {
                const uint32_t ad = su + aRow[mi] + ca;
                ldsm4(ah[mi], ad);
                ldsm4(al[mi], ad + 16384);
            }
#pragma unroll
            for (int nj2 = 0; nj2 < 2; nj2++) {
                const uint32_t bd = su + 32768 + bRow[nj2] + cb;
                ldsm4(bh[nj2], bd);
                ldsm4(bl[nj2], bd + 16384);
            }
            // main term: fp32 accumulate
#pragma unroll
            for (int mi = 0; mi < 4; mi++)
#pragma unroll
                for (int nj = 0; nj < 4; nj++)
                    mma_f32acc(acc[mi][nj], ah[mi], &bh[nj >> 1][(nj & 1) * 2]);
            // correction terms: fp16 accumulate, shared accumulator
#pragma unroll
            for (int mi = 0; mi < 4; mi++)
#pragma unroll
                for (int nj = 0; nj < 4; nj++)
                    mma_f16acc(accc[mi][nj], ah[mi], &bl[nj >> 1][(nj & 1) * 2]);
#pragma unroll
            for (int mi = 0; mi < 4; mi++)
#pragma unroll
                for (int nj = 0; nj < 4; nj++)
                    mma_f16acc(accc[mi][nj], al[mi], &bh[nj >> 1][(nj & 1) * 2]);
        }
        __syncthreads();
        if (hs < 6) { load_half(hs + 2); CP_COMMIT(); }
    }

    const int r0 = lane >> 2;
    const int c0 = (lane & 3) * 2;
#pragma unroll
    for (int mi = 0; mi < 4; mi++) {
        const int gm = bm + wm + mi * 16 + r0;
#pragma unroll
        for (int half = 0; half < 2; half++) {
            const int gmr = gm + half * 8;
            if (gmr < M) {
                float* op = Cmat + (size_t)gmr * N + bn;
#pragma unroll
                for (int nj = 0; nj < 4; nj++) {
                    const int cl = wn + nj * 8 + c0;
                    const float2 cr = __half22float2(*(__half2*)&accc[mi][nj][half]);
                    float2 o;
                    o.x = acc[mi][nj][half * 2 + 0] + cr.x + pbias[cl];
                    o.y = acc[mi][nj][half * 2 + 1] + cr.y + pbias[cl + 1];
                    *(float2*)(op + cl) = o;
                }
            }
        }
    }
}

// ---------------- sampling: softmax + quad-channel bilinear gather -------
__global__ void __launch_bounds__(256) sample_kernel(
    const float* __restrict__ ref)
{
    constexpr int LH[4]  = {100, 50, 25, 13};
    constexpr int LW[4]  = {150, 75, 38, 19};
    constexpr int LST[4] = {0, 15000, 18750, 19700};

    const int warp = (blockIdx.x * blockDim.x + threadIdx.x) >> 5;
    const int lane = threadIdx.x & 31;
    if (warp >= BB * NQ * NHD) return;

    const int h  = warp % NHD;
    const int bq = warp / NHD;
    const int b  = bq / NQ;
    const int sl = (lane >> 2) & 3;

    const float* qrow = g_qout + (size_t)bq * 384;

    const float* logit = qrow + 256 + h * 16;
    float lg = (lane < 16) ? logit[lane] : -1e30f;
    float mxv = lg;
#pragma unroll
    for (int o = 8; o; o >>= 1) mxv = fmaxf(mxv, __shfl_xor_sync(0xffffffffu, mxv, o, 16));
    float ev = __expf(lg - mxv);
    float sum = ev;
#pragma unroll
    for (int o = 8; o; o >>= 1) sum += __shfl_xor_sync(0xffffffffu, sum, o, 16);
    const float aw = ev / sum;

    const float2 off2 = ((const float2*)(qrow + h * 32))[lane & 15];
    const float2 rxy  = ((const float2*)(ref + (size_t)bq * 8))[sl];
    const float fW = (float)LW[sl], fH = (float)LH[sl];
    const float x = (rxy.x + off2.x / fW) * fW - 0.5f;
    const float y = (rxy.y + off2.y / fH) * fH - 0.5f;
    const float x0f = floorf(x), y0f = floorf(y);
    const float wx1 = x - x0f, wy1 = y - y0f;
    const int pk = (((int)y0f) << 16) | (((int)x0f) & 0xffff);
    const float wy0a_o = (1.f - wy1) * aw;
    const float wy1a_o = wy1 * aw;

    const int grp  = lane >> 3;
    const int chan = (lane & 7) * 4;
    float a0 = 0.f, a1 = 0.f, a2 = 0.f, a3 = 0.f;

#pragma unroll
    for (int l = 0; l < 4; l++) {
        const int W = LW[l], H = LH[l];
        const float* vbase = g_value
            + ((size_t)(b * S_TOT + LST[l]) * NHD + h) * DH + chan;
        const int src = l * 4 + grp;
        const int   bpk  = __shfl_sync(0xffffffffu, pk,     src);
        const float bwx  = __shfl_sync(0xffffffffu, wx1,    src);
        const float wy0a = __shfl_sync(0xffffffffu, wy0a_o, src);
        const float wy1a = __shfl_sync(0xffffffffu, wy1a_o, src);
        const int bix = (int)(short)(bpk & 0xffff);
        const int biy = bpk >> 16;
        const float wx0 = 1.f - bwx;
        const bool xi0 = (unsigned)bix < (unsigned)W;
        const bool xi1 = (unsigned)(bix + 1) < (unsigned)W;
        const bool yi0 = (unsigned)biy < (unsigned)H;
        const bool yi1 = (unsigned)(biy + 1) < (unsigned)H;
        const float* pp0 = vbase + (ptrdiff_t)(biy * W + bix) * 256;
        if (yi0 && xi0) { const float4 v = *(const float4*)pp0;
            const float w = wx0 * wy0a;
            a0 = fmaf(w, v.x, a0); a1 = fmaf(w, v.y, a1);
            a2 = fmaf(w, v.z, a2); a3 = fmaf(w, v.w, a3); }
        if (yi0 && xi1) { const float4 v = *(const float4*)(pp0 + 256);
            const float w = bwx * wy0a;
            a0 = fmaf(w, v.x, a0); a1 = fmaf(w, v.y, a1);
            a2 = fmaf(w, v.z, a2); a3 = fmaf(w, v.w, a3); }
        if (yi1 && xi0) { const float4 v = *(const float4*)(pp0 + W * 256);
            const float w = wx0 * wy1a;
            a0 = fmaf(w, v.x, a0); a1 = fmaf(w, v.y, a1);
            a2 = fmaf(w, v.z, a2); a3 = fmaf(w, v.w, a3); }
        if (yi1 && xi1) { const float4 v = *(const float4*)(pp0 + W * 256 + 256);
            const float w = bwx * wy1a;
            a0 = fmaf(w, v.x, a0); a1 = fmaf(w, v.y, a1);
            a2 = fmaf(w, v.z, a2); a3 = fmaf(w, v.w, a3); }
    }
#pragma unroll
    for (int o = 8; o <= 16; o <<= 1) {
        a0 += __shfl_xor_sync(0xffffffffu, a0, o);
        a1 += __shfl_xor_sync(0xffffffffu, a1, o);
        a2 += __shfl_xor_sync(0xffffffffu, a2, o);
        a3 += __shfl_xor_sync(0xffffffffu, a3, o);
    }

    if (lane < 8) {
        __half h0 = __float2half_rn(a0), h1 = __float2half_rn(a1);
        __half h2 = __float2half_rn(a2), h3 = __float2half_rn(a3);
        __half l0 = __float2half_rn(a0 - __half2float(h0));
        __half l1 = __float2half_rn(a1 - __half2float(h1));
        __half l2 = __float2half_rn(a2 - __half2float(h2));
        __half l3 = __float2half_rn(a3 - __half2float(h3));
        uint2 hp, lp;
        hp.x = (uint32_t)__half_as_ushort(h0) | ((uint32_t)__half_as_ushort(h1) << 16);
        hp.y = (uint32_t)__half_as_ushort(h2) | ((uint32_t)__half_as_ushort(h3) << 16);
        lp.x = (uint32_t)__half_as_ushort(l0) | ((uint32_t)__half_as_ushort(l1) << 16);
        lp.y = (uint32_t)__half_as_ushort(l2) | ((uint32_t)__half_as_ushort(l3) << 16);
        const size_t q2 = (size_t)(bq * NHD + h) * 8 + (lane & 7);
        ((uint2*)g_s_hi)[q2] = hp;
        ((uint2*)g_s_lo)[q2] = lp;
    }
}

// ---------------- launch ----------------
#define GEMM_SMEM_BYTES 67584

extern "C" void kernel_launch(void* const* d_in, const int* in_sizes, int n_in,
                              void* d_out, int out_size)
{
    (void)in_sizes; (void)n_in; (void)out_size;
    const float* query  = (const float*)d_in[0];
    const float* vlv    = (const float*)d_in[1];
    const float* refpts = (const float*)d_in[2];
    const float* W_off  = (const float*)d_in[4];
    const float* b_off  = (const float*)d_in[5];
    const float* W_attn = (const float*)d_in[6];
    const float* b_attn = (const float*)d_in[7];
    const float* W_val  = (const float*)d_in[8];
    const float* b_val  = (const float*)d_in[9];
    const float* W_out  = (const float*)d_in[10];
    const float* b_out  = (const float*)d_in[11];
    float* out = (float*)d_out;

    cudaFuncSetAttribute(gemm_tc2_kernel,
                         cudaFuncAttributeMaxDynamicSharedMemorySize, GEMM_SMEM_BYTES);

    float *p_value, *p_qout, *p_qb;
    __half *p_vhi, *p_vlo, *p_qhi, *p_qlo, *p_shi, *p_slo, *p_whi, *p_wlo;
    cudaGetSymbolAddress((void**)&p_value, g_value);
    cudaGetSymbolAddress((void**)&p_qout,  g_qout);
    cudaGetSymbolAddress((void**)&p_qb,    g_qb);
    cudaGetSymbolAddress((void**)&p_vhi,   g_v_hi);
    cudaGetSymbolAddress((void**)&p_vlo,   g_v_lo);
    cudaGetSymbolAddress((void**)&p_qhi,   g_q_hi);
    cudaGetSymbolAddress((void**)&p_qlo,   g_q_lo);
    cudaGetSymbolAddress((void**)&p_shi,   g_s_hi);
    cudaGetSymbolAddress((void**)&p_slo,   g_s_lo);
    cudaGetSymbolAddress((void**)&p_whi,   g_w_hi);
    cudaGetSymbolAddress((void**)&p_wlo,   g_w_lo);

    __half *wv_hi = p_whi,           *wv_lo = p_wlo;
    __half *qw_hi = p_whi + 65536,   *qw_lo = p_wlo + 65536;
    __half *wu_hi = p_whi + 163840,  *wu_lo = p_wlo + 163840;

    {
        ConvArgs ca;
        ca.vlv = vlv; ca.query = query;
        ca.w_val = W_val; ca.w_off = W_off; ca.w_attn = W_attn; ca.w_out = W_out;
        ca.b_off = b_off; ca.b_attn = b_attn;
        convert_all_kernel<<<NB_TOT, 256>>>(ca);
    }

    {
        GemmSeg sv, sq;
        sv.Ahi = p_vhi; sv.Alo = p_vlo; sv.Bhi = wv_hi; sv.Blo = wv_lo;
        sv.bias = b_val; sv.C = p_value; sv.M = MV; sv.N = 256;
        sv.tilesPerRow = 2; sv.ntiles = ((MV + 127) / 128) * 2;
        sq.Ahi = p_qhi; sq.Alo = p_qlo; sq.Bhi = qw_hi; sq.Blo = qw_lo;
        sq.bias = p_qb; sq.C = p_qout; sq.M = MQ; sq.N = 384;
        sq.tilesPerRow = 3; sq.ntiles = (MQ / 128) * 3;
        gemm_tc2_kernel<<<sv.ntiles + sq.ntiles, 256, GEMM_SMEM_BYTES>>>(sv, sq);
    }

    {
        const int nwarp = BB * NQ * NHD;
        sample_kernel<<<(nwarp * 32 + 255) / 256, 256>>>(refpts);
    }

    {
        GemmSeg so, dummy;
        so.Ahi = p_shi; so.Alo = p_slo; so.Bhi = wu_hi; so.Blo = wu_lo;
        so.bias = b_out; so.C = out; so.M = MQ; so.N = 256;
        so.tilesPerRow = 2; so.ntiles = (MQ / 128) * 2;
        dummy = so; dummy.ntiles = 0;
        gemm_tc2_kernel<<<so.ntiles, 256, GEMM_SMEM_BYTES>>>(so, dummy);
    }
}

// round 12
// speedup vs baseline: 1.3479x; 1.3479x over previous
#include <cuda_runtime.h>
#include <cuda_fp16.h>
#include <cstdint>
#include <math.h>

// ---------------- problem constants ----------------
#define BB   4
#define NQ   8000
#define CC   256
#define NHD  8
#define NLV  4
#define NPT  4
#define DH   32
#define S_TOT 19947

#define MV (BB * S_TOT)   // 79788
#define MQ (BB * NQ)      // 32000

// ---------------- scratch ----------------
__device__ float g_value[(size_t)MV * CC];
__device__ float g_qout [(size_t)MQ * 384];
__device__ __half g_v_hi [(size_t)MV * CC];
__device__ __half g_q_hi [(size_t)MQ * CC];
__device__ __half g_s_hi [(size_t)MQ * CC];
__device__ __half g_w_hi [65536 + 98304 + 65536];
__device__ __half g_w_lo [65536 + 98304 + 65536];
__device__ float g_qb[384];

// ---------------- helpers ----------------
__device__ __forceinline__ uint32_t smem_u32(const void* p) {
    uint32_t a;
    asm("{ .reg .u64 t; cvta.to.shared.u64 t, %1; cvt.u32.u64 %0, t; }" : "=r"(a) : "l"(p));
    return a;
}
__device__ __forceinline__ void ldsm4(uint32_t* r, uint32_t addr) {
    asm volatile("ldmatrix.sync.aligned.m8n8.x4.shared.b16 {%0,%1,%2,%3}, [%4];"
        : "=r"(r[0]), "=r"(r[1]), "=r"(r[2]), "=r"(r[3]) : "r"(addr));
}
__device__ __forceinline__ void mma_f32acc(float* c, const uint32_t* a, const uint32_t* b) {
    asm volatile(
        "mma.sync.aligned.m16n8k16.row.col.f32.f16.f16.f32 "
        "{%0,%1,%2,%3}, {%4,%5,%6,%7}, {%8,%9}, {%0,%1,%2,%3};"
        : "+f"(c[0]), "+f"(c[1]), "+f"(c[2]), "+f"(c[3])
        : "r"(a[0]), "r"(a[1]), "r"(a[2]), "r"(a[3]), "r"(b[0]), "r"(b[1]));
}
__device__ __forceinline__ void cp_async16(uint32_t dst, const void* src, uint32_t sz) {
    asm volatile("cp.async.cg.shared.global [%0], [%1], 16, %2;"
        :: "r"(dst), "l"(src), "r"(sz) : "memory");
}
#define CP_COMMIT() asm volatile("cp.async.commit_group;" ::: "memory")
#define CP_WAIT(n)  asm volatile("cp.async.wait_group %0;" :: "n"(n) : "memory")

// ---------------- mega conversion kernel -------------------------------
// value/query: fp16 hi only. weights: fp16 hi + lo. bias: fuse.
#define NB_V  (MV / 4)
#define NB_Q  (MQ / 4)
#define NB_WV 64
#define NB_WO 64
#define NB_WA 32
#define NB_WU 64
#define NB_TOT (NB_V + NB_Q + NB_WV + NB_WO + NB_WA + NB_WU + 1)

struct ConvArgs {
    const float *vlv, *query, *w_val, *w_off, *w_attn, *w_out, *b_off, *b_attn;
};

__global__ void __launch_bounds__(256) convert_all_kernel(ConvArgs a)
{
    const int blk = blockIdx.x;
    const int tid = threadIdx.x;

    const float* src;
    uint2 *hi, *lo = nullptr;
    int rel;

    if (blk < NB_V) {
        src = a.vlv; hi = (uint2*)g_v_hi; rel = blk;
    } else if (blk < NB_V + NB_Q) {
        src = a.query; hi = (uint2*)g_q_hi; rel = blk - NB_V;
    } else if (blk < NB_V + NB_Q + NB_WV) {
        src = a.w_val; hi = (uint2*)g_w_hi; lo = (uint2*)g_w_lo; rel = blk - (NB_V + NB_Q);
    } else if (blk < NB_V + NB_Q + NB_WV + NB_WO) {
        src = a.w_off; hi = (uint2*)(g_w_hi + 65536); lo = (uint2*)(g_w_lo + 65536);
        rel = blk - (NB_V + NB_Q + NB_WV);
    } else if (blk < NB_V + NB_Q + NB_WV + NB_WO + NB_WA) {
        src = a.w_attn; hi = (uint2*)(g_w_hi + 131072); lo = (uint2*)(g_w_lo + 131072);
        rel = blk - (NB_V + NB_Q + NB_WV + NB_WO);
    } else if (blk < NB_V + NB_Q + NB_WV + NB_WO + NB_WA + NB_WU) {
        src = a.w_out; hi = (uint2*)(g_w_hi + 163840); lo = (uint2*)(g_w_lo + 163840);
        rel = blk - (NB_V + NB_Q + NB_WV + NB_WO + NB_WA);
    } else {
        for (int i = tid; i < 384; i += 256)
            g_qb[i] = (i < 256) ? a.b_off[i] : a.b_attn[i - 256];
        return;
    }

    const int i = rel * 256 + tid;
    const float4 v = ((const float4*)src)[i];
    __half h0 = __float2half_rn(v.x), h1 = __float2half_rn(v.y);
    __half h2 = __float2half_rn(v.z), h3 = __float2half_rn(v.w);
    uint2 hp;
    hp.x = (uint32_t)__half_as_ushort(h0) | ((uint32_t)__half_as_ushort(h1) << 16);
    hp.y = (uint32_t)__half_as_ushort(h2) | ((uint32_t)__half_as_ushort(h3) << 16);
    hi[i] = hp;
    if (lo) {
        __half l0 = __float2half_rn(v.x - __half2float(h0));
        __half l1 = __float2half_rn(v.y - __half2float(h1));
        __half l2 = __float2half_rn(v.z - __half2float(h2));
        __half l3 = __float2half_rn(v.w - __half2float(h3));
        uint2 lp;
        lp.x = (uint32_t)__half_as_ushort(l0) | ((uint32_t)__half_as_ushort(l1) << 16);
        lp.y = (uint32_t)__half_as_ushort(l2) | ((uint32_t)__half_as_ushort(l3) << 16);
        lo[i] = lp;
    }
}

// ============ HMMA GEMM: 2-term (Ah*Bh + Ah*Bl), 128 thr, 64x64 warp tile ============
// tile 128x128, K in 8 half-stages of 32. smem 48KB: Ahi | Bhi | Blo planes of 16KB.
struct GemmSeg {
    const __half *Ahi, *Bhi, *Blo;
    const float* bias;
    float* C;
    int M, N, ntiles, tilesPerRow;
};

__global__ void __launch_bounds__(128, 2) gemm_tc2_kernel(GemmSeg s0, GemmSeg s1)
{
    extern __shared__ char smraw[];
    char* sm = (char*)(((uintptr_t)smraw + 1023) & ~(uintptr_t)1023);
    const uint32_t su = smem_u32(sm);
    float* pbias = (float*)(sm + 49152);

    int t = blockIdx.x;
    const __half *Ahi, *Bhi, *Blo;
    const float* bias;
    float* Cmat;
    int M, N, tpr;
    if (t < s0.ntiles) {
        Ahi = s0.Ahi; Bhi = s0.Bhi; Blo = s0.Blo;
        bias = s0.bias; Cmat = s0.C; M = s0.M; N = s0.N; tpr = s0.tilesPerRow;
    } else {
        t -= s0.ntiles;
        Ahi = s1.Ahi; Bhi = s1.Bhi; Blo = s1.Blo;
        bias = s1.bias; Cmat = s1.C; M = s1.M; N = s1.N; tpr = s1.tilesPerRow;
    }
    const int bm = (t / tpr) * 128;
    const int bn = (t % tpr) * 128;

    const int tid  = threadIdx.x;
    const int lane = tid & 31;
    const int warp = tid >> 5;            // 0..3
    const int wm = (warp >> 1) * 64;      // 2x2 warp layout, 64x64 tiles
    const int wn = (warp & 1) * 64;

    pbias[tid] = bias[bn + tid];

    float acc[4][8][4];
#pragma unroll
    for (int i = 0; i < 4; i++)
#pragma unroll
        for (int j = 0; j < 8; j++)
#pragma unroll
            for (int k = 0; k < 4; k++) acc[i][j][k] = 0.f;

    const uint32_t mx = (uint32_t)((lane & 7) << 4);
    uint32_t aRow[4], bRow[4];
#pragma unroll
    for (int mi = 0; mi < 4; mi++)
        aRow[mi] = (uint32_t)((wm + mi * 16 + (lane & 15)) * 128);
    const uint32_t colA = (uint32_t)((lane >> 4) * 16);
#pragma unroll
    for (int nj2 = 0; nj2 < 4; nj2++)
        bRow[nj2] = (uint32_t)((wn + nj2 * 16 + (lane & 7) + ((lane >> 4) & 1) * 8) * 128);
    const uint32_t colB = (uint32_t)(((lane >> 3) & 1) * 16);

    // one K-32 half-stage into half (hs&1) of the 3 planes; 128 threads, 12 cp.async each
    auto load_half = [&](int hs) {
        const int hb = (hs & 1) * 64;
        const int ksrc = hs * 64;
#pragma unroll
        for (int pl = 0; pl < 3; pl++) {
            const __half* gsrc = (pl == 0) ? Ahi : (pl == 1) ? Bhi : Blo;
            const bool isA = (pl == 0);
            const uint32_t pbase = su + (uint32_t)pl * 16384u;
#pragma unroll
            for (int it = 0; it < 4; it++) {
                const int idx = it * 128 + tid;        // 0..511
                const int r = idx >> 2;
                const int c = idx & 3;
                const uint32_t doff = (uint32_t)(r * 128)
                    + (uint32_t)((hb + c * 16) ^ ((r & 7) << 4));
                const int grow = (isA ? bm : bn) + r;
                const uint32_t sz = (isA && grow >= M) ? 0u : 16u;
                const size_t soff = (size_t)grow * 512 + ksrc + c * 16;
                cp_async16(pbase + doff, (const char*)gsrc + soff, sz);
            }
        }
    };

    load_half(0); CP_COMMIT();
    load_half(1); CP_COMMIT();

    for (int hs = 0; hs < 8; hs++) {
        if (hs < 7) CP_WAIT(1); else CP_WAIT(0);
        __syncthreads();

        const uint32_t hb = (uint32_t)((hs & 1) * 64);
#pragma unroll
        for (int kk = 0; kk < 2; kk++) {
            uint32_t ah[4][4], bh[4][4], bl[4][4];
            const uint32_t ca = (hb + (uint32_t)(kk * 32) + colA) ^ mx;
            const uint32_t cb = (hb + (uint32_t)(kk * 32) + colB) ^ mx;
#pragma unroll
            for (int mi = 0; mi < 4; mi++)
                ldsm4(ah[mi], su + aRow[mi] + ca);
#pragma unroll
            for (int nj2 = 0; nj2 < 4; nj2++) {
                const uint32_t bd = su + 16384 + bRow[nj2] + cb;
                ldsm4(bh[nj2], bd);
                ldsm4(bl[nj2], bd + 16384);
            }
#pragma unroll
            for (int mi = 0; mi < 4; mi++)
#pragma unroll
                for (int nj = 0; nj < 8; nj++)
                    mma_f32acc(acc[mi][nj], ah[mi], &bh[nj >> 1][(nj & 1) * 2]);
#pragma unroll
            for (int mi = 0; mi < 4; mi++)
#pragma unroll
                for (int nj = 0; nj < 8; nj++)
                    mma_f32acc(acc[mi][nj], ah[mi], &bl[nj >> 1][(nj & 1) * 2]);
        }
        __syncthreads();
        if (hs < 6) { load_half(hs + 2); CP_COMMIT(); }
    }

    const int r0 = lane >> 2;
    const int c0 = (lane & 3) * 2;
#pragma unroll
    for (int mi = 0; mi < 4; mi++) {
        const int gm = bm + wm + mi * 16 + r0;
#pragma unroll
        for (int half = 0; half < 2; half++) {
            const int gmr = gm + half * 8;
            if (gmr < M) {
                float* op = Cmat + (size_t)gmr * N + bn;
#pragma unroll
                for (int nj = 0; nj < 8; nj++) {
                    const int cl = wn + nj * 8 + c0;
                    float2 o;
                    o.x = acc[mi][nj][half * 2 + 0] + pbias[cl];
                    o.y = acc[mi][nj][half * 2 + 1] + pbias[cl + 1];
                    *(float2*)(op + cl) = o;
                }
            }
        }
    }
}

// ---------------- sampling: softmax + quad-channel bilinear gather -------
__global__ void __launch_bounds__(256) sample_kernel(
    const float* __restrict__ ref)
{
    constexpr int LH[4]  = {100, 50, 25, 13};
    constexpr int LW[4]  = {150, 75, 38, 19};
    constexpr int LST[4] = {0, 15000, 18750, 19700};

    const int warp = (blockIdx.x * blockDim.x + threadIdx.x) >> 5;
    const int lane = threadIdx.x & 31;
    if (warp >= BB * NQ * NHD) return;

    const int h  = warp % NHD;
    const int bq = warp / NHD;
    const int b  = bq / NQ;
    const int sl = (lane >> 2) & 3;

    const float* qrow = g_qout + (size_t)bq * 384;

    const float* logit = qrow + 256 + h * 16;
    float lg = (lane < 16) ? logit[lane] : -1e30f;
    float mxv = lg;
#pragma unroll
    for (int o = 8; o; o >>= 1) mxv = fmaxf(mxv, __shfl_xor_sync(0xffffffffu, mxv, o, 16));
    float ev = __expf(lg - mxv);
    float sum = ev;
#pragma unroll
    for (int o = 8; o; o >>= 1) sum += __shfl_xor_sync(0xffffffffu, sum, o, 16);
    const float aw = ev / sum;

    const float2 off2 = ((const float2*)(qrow + h * 32))[lane & 15];
    const float2 rxy  = ((const float2*)(ref + (size_t)bq * 8))[sl];
    const float fW = (float)LW[sl], fH = (float)LH[sl];
    const float x = (rxy.x + off2.x / fW) * fW - 0.5f;
    const float y = (rxy.y + off2.y / fH) * fH - 0.5f;
    const float x0f = floorf(x), y0f = floorf(y);
    const float wx1 = x - x0f, wy1 = y - y0f;
    const int pk = (((int)y0f) << 16) | (((int)x0f) & 0xffff);
    const float wy0a_o = (1.f - wy1) * aw;
    const float wy1a_o = wy1 * aw;

    const int grp  = lane >> 3;
    const int chan = (lane & 7) * 4;
    float a0 = 0.f, a1 = 0.f, a2 = 0.f, a3 = 0.f;

#pragma unroll
    for (int l = 0; l < 4; l++) {
        const int W = LW[l], H = LH[l];
        const float* vbase = g_value
            + ((size_t)(b * S_TOT + LST[l]) * NHD + h) * DH + chan;
        const int src = l * 4 + grp;
        const int   bpk  = __shfl_sync(0xffffffffu, pk,     src);
        const float bwx  = __shfl_sync(0xffffffffu, wx1,    src);
        const float wy0a = __shfl_sync(0xffffffffu, wy0a_o, src);
        const float wy1a = __shfl_sync(0xffffffffu, wy1a_o, src);
        const int bix = (int)(short)(bpk & 0xffff);
        const int biy = bpk >> 16;
        const float wx0 = 1.f - bwx;
        const bool xi0 = (unsigned)bix < (unsigned)W;
        const bool xi1 = (unsigned)(bix + 1) < (unsigned)W;
        const bool yi0 = (unsigned)biy < (unsigned)H;
        const bool yi1 = (unsigned)(biy + 1) < (unsigned)H;
        const float* pp0 = vbase + (ptrdiff_t)(biy * W + bix) * 256;
        if (yi0 && xi0) { const float4 v = *(const float4*)pp0;
            const float w = wx0 * wy0a;
            a0 = fmaf(w, v.x, a0); a1 = fmaf(w, v.y, a1);
            a2 = fmaf(w, v.z, a2); a3 = fmaf(w, v.w, a3); }
        if (yi0 && xi1) { const float4 v = *(const float4*)(pp0 + 256);
            const float w = bwx * wy0a;
            a0 = fmaf(w, v.x, a0); a1 = fmaf(w, v.y, a1);
            a2 = fmaf(w, v.z, a2); a3 = fmaf(w, v.w, a3); }
        if (yi1 && xi0) { const float4 v = *(const float4*)(pp0 + W * 256);
            const float w = wx0 * wy1a;
            a0 = fmaf(w, v.x, a0); a1 = fmaf(w, v.y, a1);
            a2 = fmaf(w, v.z, a2); a3 = fmaf(w, v.w, a3); }
        if (yi1 && xi1) { const float4 v = *(const float4*)(pp0 + W * 256 + 256);
            const float w = bwx * wy1a;
            a0 = fmaf(w, v.x, a0); a1 = fmaf(w, v.y, a1);
            a2 = fmaf(w, v.z, a2); a3 = fmaf(w, v.w, a3); }
    }
#pragma unroll
    for (int o = 8; o <= 16; o <<= 1) {
        a0 += __shfl_xor_sync(0xffffffffu, a0, o);
        a1 += __shfl_xor_sync(0xffffffffu, a1, o);
        a2 += __shfl_xor_sync(0xffffffffu, a2, o);
        a3 += __shfl_xor_sync(0xffffffffu, a3, o);
    }

    if (lane < 8) {
        __half h0 = __float2half_rn(a0), h1 = __float2half_rn(a1);
        __half h2 = __float2half_rn(a2), h3 = __float2half_rn(a3);
        uint2 hp;
        hp.x = (uint32_t)__half_as_ushort(h0) | ((uint32_t)__half_as_ushort(h1) << 16);
        hp.y = (uint32_t)__half_as_ushort(h2) | ((uint32_t)__half_as_ushort(h3) << 16);
        const size_t q2 = (size_t)(bq * NHD + h) * 8 + (lane & 7);
        ((uint2*)g_s_hi)[q2] = hp;
    }
}

// ---------------- launch ----------------
#define GEMM_SMEM_BYTES 50688

extern "C" void kernel_launch(void* const* d_in, const int* in_sizes, int n_in,
                              void* d_out, int out_size)
{
    (void)in_sizes; (void)n_in; (void)out_size;
    const float* query  = (const float*)d_in[0];
    const float* vlv    = (const float*)d_in[1];
    const float* refpts = (const float*)d_in[2];
    const float* W_off  = (const float*)d_in[4];
    const float* b_off  = (const float*)d_in[5];
    const float* W_attn = (const float*)d_in[6];
    const float* b_attn = (const float*)d_in[7];
    const float* W_val  = (const float*)d_in[8];
    const float* b_val  = (const float*)d_in[9];
    const float* W_out  = (const float*)d_in[10];
    const float* b_out  = (const float*)d_in[11];
    float* out = (float*)d_out;

    cudaFuncSetAttribute(gemm_tc2_kernel,
                         cudaFuncAttributeMaxDynamicSharedMemorySize, GEMM_SMEM_BYTES);

    float *p_value, *p_qout, *p_qb;
    __half *p_vhi, *p_qhi, *p_shi, *p_whi, *p_wlo;
    cudaGetSymbolAddress((void**)&p_value, g_value);
    cudaGetSymbolAddress((void**)&p_qout,  g_qout);
    cudaGetSymbolAddress((void**)&p_qb,    g_qb);
    cudaGetSymbolAddress((void**)&p_vhi,   g_v_hi);
    cudaGetSymbolAddress((void**)&p_qhi,   g_q_hi);
    cudaGetSymbolAddress((void**)&p_shi,   g_s_hi);
    cudaGetSymbolAddress((void**)&p_whi,   g_w_hi);
    cudaGetSymbolAddress((void**)&p_wlo,   g_w_lo);

    __half *wv_hi = p_whi,           *wv_lo = p_wlo;
    __half *qw_hi = p_whi + 65536,   *qw_lo = p_wlo + 65536;
    __half *wu_hi = p_whi + 163840,  *wu_lo = p_wlo + 163840;

    {
        ConvArgs ca;
        ca.vlv = vlv; ca.query = query;
        ca.w_val = W_val; ca.w_off = W_off; ca.w_attn = W_attn; ca.w_out = W_out;
        ca.b_off = b_off; ca.b_attn = b_attn;
        convert_all_kernel<<<NB_TOT, 256>>>(ca);
    }

    {
        GemmSeg sv, sq;
        sv.Ahi = p_vhi; sv.Bhi = wv_hi; sv.Blo = wv_lo;
        sv.bias = b_val; sv.C = p_value; sv.M = MV; sv.N = 256;
        sv.tilesPerRow = 2; sv.ntiles = ((MV + 127) / 128) * 2;
        sq.Ahi = p_qhi; sq.Bhi = qw_hi; sq.Blo = qw_lo;
        sq.bias = p_qb; sq.C = p_qout; sq.M = MQ; sq.N = 384;
        sq.tilesPerRow = 3; sq.ntiles = (MQ / 128) * 3;
        gemm_tc2_kernel<<<sv.ntiles + sq.ntiles, 128, GEMM_SMEM_BYTES>>>(sv, sq);
    }

    {
        const int nwarp = BB * NQ * NHD;
        sample_kernel<<<(nwarp * 32 + 255) / 256, 256>>>(refpts);
    }

    {
        GemmSeg so, dummy;
        so.Ahi = p_shi; so.Bhi = wu_hi; so.Blo = wu_lo;
        so.bias = b_out; so.C = out; so.M = MQ; so.N = 256;
        so.tilesPerRow = 2; so.ntiles = (MQ / 128) * 2;
        dummy = so; dummy.ntiles = 0;
        gemm_tc2_kernel<<<so.ntiles, 128, GEMM_SMEM_BYTES>>>(so, dummy);
    }
}

// round 13
// speedup vs baseline: 1.5030x; 1.1151x over previous
#include <cuda_runtime.h>
#include <cuda_fp16.h>
#include <cstdint>
#include <math.h>

// ---------------- problem constants ----------------
#define BB   4
#define NQ   8000
#define CC   256
#define NHD  8
#define NLV  4
#define NPT  4
#define DH   32
#define S_TOT 19947

#define MV (BB * S_TOT)   // 79788
#define MQ (BB * NQ)      // 32000

// ---------------- scratch ----------------
__device__ float g_value[(size_t)MV * CC];
__device__ float g_qout [(size_t)MQ * 384];
__device__ __half g_v_hi [(size_t)MV * CC];
__device__ __half g_q_hi [(size_t)MQ * CC];
__device__ __half g_s_hi [(size_t)MQ * CC];
__device__ __half g_w_hi [65536 + 98304 + 65536];
__device__ float g_qb[384];

// ---------------- helpers ----------------
__device__ __forceinline__ uint32_t smem_u32(const void* p) {
    uint32_t a;
    asm("{ .reg .u64 t; cvta.to.shared.u64 t, %1; cvt.u32.u64 %0, t; }" : "=r"(a) : "l"(p));
    return a;
}
__device__ __forceinline__ void ldsm4(uint32_t* r, uint32_t addr) {
    asm volatile("ldmatrix.sync.aligned.m8n8.x4.shared.b16 {%0,%1,%2,%3}, [%4];"
        : "=r"(r[0]), "=r"(r[1]), "=r"(r[2]), "=r"(r[3]) : "r"(addr));
}
__device__ __forceinline__ void mma_f32acc(float* c, const uint32_t* a, const uint32_t* b) {
    asm volatile(
        "mma.sync.aligned.m16n8k16.row.col.f32.f16.f16.f32 "
        "{%0,%1,%2,%3}, {%4,%5,%6,%7}, {%8,%9}, {%0,%1,%2,%3};"
        : "+f"(c[0]), "+f"(c[1]), "+f"(c[2]), "+f"(c[3])
        : "r"(a[0]), "r"(a[1]), "r"(a[2]), "r"(a[3]), "r"(b[0]), "r"(b[1]));
}
__device__ __forceinline__ void cp_async16(uint32_t dst, const void* src, uint32_t sz) {
    asm volatile("cp.async.cg.shared.global [%0], [%1], 16, %2;"
        :: "r"(dst), "l"(src), "r"(sz) : "memory");
}
#define CP_COMMIT() asm volatile("cp.async.commit_group;" ::: "memory")
#define CP_WAIT(n)  asm volatile("cp.async.wait_group %0;" :: "n"(n) : "memory")

// ---------------- mega conversion kernel (fp32 -> fp16 hi only) --------
#define NB_V  (MV / 4)
#define NB_Q  (MQ / 4)
#define NB_WV 64
#define NB_WO 64
#define NB_WA 32
#define NB_WU 64
#define NB_TOT (NB_V + NB_Q + NB_WV + NB_WO + NB_WA + NB_WU + 1)

struct ConvArgs {
    const float *vlv, *query, *w_val, *w_off, *w_attn, *w_out, *b_off, *b_attn;
};

__global__ void __launch_bounds__(256) convert_all_kernel(ConvArgs a)
{
    const int blk = blockIdx.x;
    const int tid = threadIdx.x;

    const float* src;
    uint2 *hi;
    int rel;

    if (blk < NB_V) {
        src = a.vlv; hi = (uint2*)g_v_hi; rel = blk;
    } else if (blk < NB_V + NB_Q) {
        src = a.query; hi = (uint2*)g_q_hi; rel = blk - NB_V;
    } else if (blk < NB_V + NB_Q + NB_WV) {
        src = a.w_val; hi = (uint2*)g_w_hi; rel = blk - (NB_V + NB_Q);
    } else if (blk < NB_V + NB_Q + NB_WV + NB_WO) {
        src = a.w_off; hi = (uint2*)(g_w_hi + 65536);
        rel = blk - (NB_V + NB_Q + NB_WV);
    } else if (blk < NB_V + NB_Q + NB_WV + NB_WO + NB_WA) {
        src = a.w_attn; hi = (uint2*)(g_w_hi + 131072);
        rel = blk - (NB_V + NB_Q + NB_WV + NB_WO);
    } else if (blk < NB_V + NB_Q + NB_WV + NB_WO + NB_WA + NB_WU) {
        src = a.w_out; hi = (uint2*)(g_w_hi + 163840);
        rel = blk - (NB_V + NB_Q + NB_WV + NB_WO + NB_WA);
    } else {
        for (int i = tid; i < 384; i += 256)
            g_qb[i] = (i < 256) ? a.b_off[i] : a.b_attn[i - 256];
        return;
    }

    const int i = rel * 256 + tid;
    const float4 v = ((const float4*)src)[i];
    __half h0 = __float2half_rn(v.x), h1 = __float2half_rn(v.y);
    __half h2 = __float2half_rn(v.z), h3 = __float2half_rn(v.w);
    uint2 hp;
    hp.x = (uint32_t)__half_as_ushort(h0) | ((uint32_t)__half_as_ushort(h1) << 16);
    hp.y = (uint32_t)__half_as_ushort(h2) | ((uint32_t)__half_as_ushort(h3) << 16);
    hi[i] = hp;
}

// ============ HMMA GEMM: pure fp16, 128 thr, 64x64 warp tile ============
// tile 128x128, K in 8 half-stages of 32. smem 32KB: A | B planes of 16KB.
struct GemmSeg {
    const __half *Ahi, *Bhi;
    const float* bias;
    float* C;
    int M, N, ntiles, tilesPerRow;
};

__global__ void __launch_bounds__(128, 2) gemm_tc2_kernel(GemmSeg s0, GemmSeg s1)
{
    extern __shared__ char smraw[];
    char* sm = (char*)(((uintptr_t)smraw + 1023) & ~(uintptr_t)1023);
    const uint32_t su = smem_u32(sm);
    float* pbias = (float*)(sm + 32768);

    int t = blockIdx.x;
    const __half *Ahi, *Bhi;
    const float* bias;
    float* Cmat;
    int M, N, tpr;
    if (t < s0.ntiles) {
        Ahi = s0.Ahi; Bhi = s0.Bhi;
        bias = s0.bias; Cmat = s0.C; M = s0.M; N = s0.N; tpr = s0.tilesPerRow;
    } else {
        t -= s0.ntiles;
        Ahi = s1.Ahi; Bhi = s1.Bhi;
        bias = s1.bias; Cmat = s1.C; M = s1.M; N = s1.N; tpr = s1.tilesPerRow;
    }
    const int bm = (t / tpr) * 128;
    const int bn = (t % tpr) * 128;

    const int tid  = threadIdx.x;
    const int lane = tid & 31;
    const int warp = tid >> 5;            // 0..3
    const int wm = (warp >> 1) * 64;      // 2x2 warp layout, 64x64 tiles
    const int wn = (warp & 1) * 64;

    pbias[tid] = bias[bn + tid];

    float acc[4][8][4];
#pragma unroll
    for (int i = 0; i < 4; i++)
#pragma unroll
        for (int j = 0; j < 8; j++)
#pragma unroll
            for (int k = 0; k < 4; k++) acc[i][j][k] = 0.f;

    const uint32_t mx = (uint32_t)((lane & 7) << 4);
    uint32_t aRow[4], bRow[4];
#pragma unroll
    for (int mi = 0; mi < 4; mi++)
        aRow[mi] = (uint32_t)((wm + mi * 16 + (lane & 15)) * 128);
    const uint32_t colA = (uint32_t)((lane >> 4) * 16);
#pragma unroll
    for (int nj2 = 0; nj2 < 4; nj2++)
        bRow[nj2] = (uint32_t)((wn + nj2 * 16 + (lane & 7) + ((lane >> 4) & 1) * 8) * 128);
    const uint32_t colB = (uint32_t)(((lane >> 3) & 1) * 16);

    // one K-32 half-stage into half (hs&1) of both planes; 128 threads, 8 cp.async each
    auto load_half = [&](int hs) {
        const int hb = (hs & 1) * 64;
        const int ksrc = hs * 64;
#pragma unroll
        for (int pl = 0; pl < 2; pl++) {
            const __half* gsrc = (pl == 0) ? Ahi : Bhi;
            const bool isA = (pl == 0);
            const uint32_t pbase = su + (uint32_t)pl * 16384u;
#pragma unroll
            for (int it = 0; it < 4; it++) {
                const int idx = it * 128 + tid;        // 0..511
                const int r = idx >> 2;
                const int c = idx & 3;
                const uint32_t doff = (uint32_t)(r * 128)
                    + (uint32_t)((hb + c * 16) ^ ((r & 7) << 4));
                const int grow = (isA ? bm : bn) + r;
                const uint32_t sz = (isA && grow >= M) ? 0u : 16u;
                const size_t soff = (size_t)grow * 512 + ksrc + c * 16;
                cp_async16(pbase + doff, (const char*)gsrc + soff, sz);
            }
        }
    };

    load_half(0); CP_COMMIT();
    load_half(1); CP_COMMIT();

    for (int hs = 0; hs < 8; hs++) {
        if (hs < 7) CP_WAIT(1); else CP_WAIT(0);
        __syncthreads();

        const uint32_t hb = (uint32_t)((hs & 1) * 64);
#pragma unroll
        for (int kk = 0; kk < 2; kk++) {
            uint32_t ah[4][4], bh[4][4];
            const uint32_t ca = (hb + (uint32_t)(kk * 32) + colA) ^ mx;
            const uint32_t cb = (hb + (uint32_t)(kk * 32) + colB) ^ mx;
#pragma unroll
            for (int mi = 0; mi < 4; mi++)
                ldsm4(ah[mi], su + aRow[mi] + ca);
#pragma unroll
            for (int nj2 = 0; nj2 < 4; nj2++)
                ldsm4(bh[nj2], su + 16384 + bRow[nj2] + cb);
#pragma unroll
            for (int mi = 0; mi < 4; mi++)
#pragma unroll
                for (int nj = 0; nj < 8; nj++)
                    mma_f32acc(acc[mi][nj], ah[mi], &bh[nj >> 1][(nj & 1) * 2]);
        }
        __syncthreads();
        if (hs < 6) { load_half(hs + 2); CP_COMMIT(); }
    }

    const int r0 = lane >> 2;
    const int c0 = (lane & 3) * 2;
#pragma unroll
    for (int mi = 0; mi < 4; mi++) {
        const int gm = bm + wm + mi * 16 + r0;
#pragma unroll
        for (int half = 0; half < 2; half++) {
            const int gmr = gm + half * 8;
            if (gmr < M) {
                float* op = Cmat + (size_t)gmr * N + bn;
#pragma unroll
                for (int nj = 0; nj < 8; nj++) {
                    const int cl = wn + nj * 8 + c0;
                    float2 o;
                    o.x = acc[mi][nj][half * 2 + 0] + pbias[cl];
                    o.y = acc[mi][nj][half * 2 + 1] + pbias[cl + 1];
                    *(float2*)(op + cl) = o;
                }
            }
        }
    }
}

// ---------------- sampling: softmax + quad-channel bilinear gather -------
__global__ void __launch_bounds__(256) sample_kernel(
    const float* __restrict__ ref)
{
    constexpr int LH[4]  = {100, 50, 25, 13};
    constexpr int LW[4]  = {150, 75, 38, 19};
    constexpr int LST[4] = {0, 15000, 18750, 19700};

    const int warp = (blockIdx.x * blockDim.x + threadIdx.x) >> 5;
    const int lane = threadIdx.x & 31;
    if (warp >= BB * NQ * NHD) return;

    const int h  = warp % NHD;
    const int bq = warp / NHD;
    const int b  = bq / NQ;
    const int sl = (lane >> 2) & 3;

    const float* qrow = g_qout + (size_t)bq * 384;

    const float* logit = qrow + 256 + h * 16;
    float lg = (lane < 16) ? logit[lane] : -1e30f;
    float mxv = lg;
#pragma unroll
    for (int o = 8; o; o >>= 1) mxv = fmaxf(mxv, __shfl_xor_sync(0xffffffffu, mxv, o, 16));
    float ev = __expf(lg - mxv);
    float sum = ev;
#pragma unroll
    for (int o = 8; o; o >>= 1) sum += __shfl_xor_sync(0xffffffffu, sum, o, 16);
    const float aw = ev / sum;

    const float2 off2 = ((const float2*)(qrow + h * 32))[lane & 15];
    const float2 rxy  = ((const float2*)(ref + (size_t)bq * 8))[sl];
    const float fW = (float)LW[sl], fH = (float)LH[sl];
    const float x = (rxy.x + off2.x / fW) * fW - 0.5f;
    const float y = (rxy.y + off2.y / fH) * fH - 0.5f;
    const float x0f = floorf(x), y0f = floorf(y);
    const float wx1 = x - x0f, wy1 = y - y0f;
    const int pk = (((int)y0f) << 16) | (((int)x0f) & 0xffff);
    const float wy0a_o = (1.f - wy1) * aw;
    const float wy1a_o = wy1 * aw;

    const int grp  = lane >> 3;
    const int chan = (lane & 7) * 4;
    float a0 = 0.f, a1 = 0.f, a2 = 0.f, a3 = 0.f;

#pragma unroll
    for (int l = 0; l < 4; l++) {
        const int W = LW[l], H = LH[l];
        const float* vbase = g_value
            + ((size_t)(b * S_TOT + LST[l]) * NHD + h) * DH + chan;
        const int src = l * 4 + grp;
        const int   bpk  = __shfl_sync(0xffffffffu, pk,     src);
        const float bwx  = __shfl_sync(0xffffffffu, wx1,    src);
        const float wy0a = __shfl_sync(0xffffffffu, wy0a_o, src);
        const float wy1a = __shfl_sync(0xffffffffu, wy1a_o, src);
        const int bix = (int)(short)(bpk & 0xffff);
        const int biy = bpk >> 16;
        const float wx0 = 1.f - bwx;
        const bool xi0 = (unsigned)bix < (unsigned)W;
        const bool xi1 = (unsigned)(bix + 1) < (unsigned)W;
        const bool yi0 = (unsigned)biy < (unsigned)H;
        const bool yi1 = (unsigned)(biy + 1) < (unsigned)H;
        const float* pp0 = vbase + (ptrdiff_t)(biy * W + bix) * 256;
        if (yi0 && xi0) { const float4 v = *(const float4*)pp0;
            const float w = wx0 * wy0a;
            a0 = fmaf(w, v.x, a0); a1 = fmaf(w, v.y, a1);
            a2 = fmaf(w, v.z, a2); a3 = fmaf(w, v.w, a3); }
        if (yi0 && xi1) { const float4 v = *(const float4*)(pp0 + 256);
            const float w = bwx * wy0a;
            a0 = fmaf(w, v.x, a0); a1 = fmaf(w, v.y, a1);
            a2 = fmaf(w, v.z, a2); a3 = fmaf(w, v.w, a3); }
        if (yi1 && xi0) { const float4 v = *(const float4*)(pp0 + W * 256);
            const float w = wx0 * wy1a;
            a0 = fmaf(w, v.x, a0); a1 = fmaf(w, v.y, a1);
            a2 = fmaf(w, v.z, a2); a3 = fmaf(w, v.w, a3); }
        if (yi1 && xi1) { const float4 v = *(const float4*)(pp0 + W * 256 + 256);
            const float w = bwx * wy1a;
            a0 = fmaf(w, v.x, a0); a1 = fmaf(w, v.y, a1);
            a2 = fmaf(w, v.z, a2); a3 = fmaf(w, v.w, a3); }
    }
#pragma unroll
    for (int o = 8; o <= 16; o <<= 1) {
        a0 += __shfl_xor_sync(0xffffffffu, a0, o);
        a1 += __shfl_xor_sync(0xffffffffu, a1, o);
        a2 += __shfl_xor_sync(0xffffffffu, a2, o);
        a3 += __shfl_xor_sync(0xffffffffu, a3, o);
    }

    if (lane < 8) {
        __half h0 = __float2half_rn(a0), h1 = __float2half_rn(a1);
        __half h2 = __float2half_rn(a2), h3 = __float2half_rn(a3);
        uint2 hp;
        hp.x = (uint32_t)__half_as_ushort(h0) | ((uint32_t)__half_as_ushort(h1) << 16);
        hp.y = (uint32_t)__half_as_ushort(h2) | ((uint32_t)__half_as_ushort(h3) << 16);
        const size_t q2 = (size_t)(bq * NHD + h) * 8 + (lane & 7);
        ((uint2*)g_s_hi)[q2] = hp;
    }
}

// ---------------- launch ----------------
#define GEMM_SMEM_BYTES 34304

extern "C" void kernel_launch(void* const* d_in, const int* in_sizes, int n_in,
                              void* d_out, int out_size)
{
    (void)in_sizes; (void)n_in; (void)out_size;
    const float* query  = (const float*)d_in[0];
    const float* vlv    = (const float*)d_in[1];
    const float* refpts = (const float*)d_in[2];
    const float* W_off  = (const float*)d_in[4];
    const float* b_off  = (const float*)d_in[5];
    const float* W_attn = (const float*)d_in[6];
    const float* b_attn = (const float*)d_in[7];
    const float* W_val  = (const float*)d_in[8];
    const float* b_val  = (const float*)d_in[9];
    const float* W_out  = (const float*)d_in[10];
    const float* b_out  = (const float*)d_in[11];
    float* out = (float*)d_out;

    cudaFuncSetAttribute(gemm_tc2_kernel,
                         cudaFuncAttributeMaxDynamicSharedMemorySize, GEMM_SMEM_BYTES);

    float *p_value, *p_qout, *p_qb;
    __half *p_vhi, *p_qhi, *p_shi, *p_whi;
    cudaGetSymbolAddress((void**)&p_value, g_value);
    cudaGetSymbolAddress((void**)&p_qout,  g_qout);
    cudaGetSymbolAddress((void**)&p_qb,    g_qb);
    cudaGetSymbolAddress((void**)&p_vhi,   g_v_hi);
    cudaGetSymbolAddress((void**)&p_qhi,   g_q_hi);
    cudaGetSymbolAddress((void**)&p_shi,   g_s_hi);
    cudaGetSymbolAddress((void**)&p_whi,   g_w_hi);

    __half *wv_hi = p_whi;
    __half *qw_hi = p_whi + 65536;
    __half *wu_hi = p_whi + 163840;

    {
        ConvArgs ca;
        ca.vlv = vlv; ca.query = query;
        ca.w_val = W_val; ca.w_off = W_off; ca.w_attn = W_attn; ca.w_out = W_out;
        ca.b_off = b_off; ca.b_attn = b_attn;
        convert_all_kernel<<<NB_TOT, 256>>>(ca);
    }

    {
        GemmSeg sv, sq;
        sv.Ahi = p_vhi; sv.Bhi = wv_hi;
        sv.bias = b_val; sv.C = p_value; sv.M = MV; sv.N = 256;
        sv.tilesPerRow = 2; sv.ntiles = ((MV + 127) / 128) * 2;
        sq.Ahi = p_qhi; sq.Bhi = qw_hi;
        sq.bias = p_qb; sq.C = p_qout; sq.M = MQ; sq.N = 384;
        sq.tilesPerRow = 3; sq.ntiles = (MQ / 128) * 3;
        gemm_tc2_kernel<<<sv.ntiles + sq.ntiles, 128, GEMM_SMEM_BYTES>>>(sv, sq);
    }

    {
        const int nwarp = BB * NQ * NHD;
        sample_kernel<<<(nwarp * 32 + 255) / 256, 256>>>(refpts);
    }

    {
        GemmSeg so, dummy;
        so.Ahi = p_shi; so.Bhi = wu_hi;
        so.bias = b_out; so.C = out; so.M = MQ; so.N = 256;
        so.tilesPerRow = 2; so.ntiles = (MQ / 128) * 2;
        dummy = so; dummy.ntiles = 0;
        gemm_tc2_kernel<<<so.ntiles, 128, GEMM_SMEM_BYTES>>>(so, dummy);
    }
}

// round 14
// speedup vs baseline: 1.7440x; 1.1603x over previous
#include <cuda_runtime.h>
#include <cuda_fp16.h>
#include <cstdint>
#include <math.h>

// ---------------- problem constants ----------------
#define BB   4
#define NQ   8000
#define CC   256
#define NHD  8
#define NLV  4
#define NPT  4
#define DH   32
#define S_TOT 19947

#define MV (BB * S_TOT)   // 79788
#define MQ (BB * NQ)      // 32000

// ---------------- scratch ----------------
__device__ __half g_value_h[(size_t)MV * CC];        // projected value, fp16 (gather src)
__device__ float  g_qout [(size_t)MQ * 384];
__device__ __half g_v_hi [(size_t)MV * CC];
__device__ __half g_q_hi [(size_t)MQ * CC];
__device__ __half g_s_hi [(size_t)MQ * CC];
__device__ __half g_w_hi [65536 + 98304 + 65536];
__device__ float  g_qb[384];

// ---------------- helpers ----------------
__device__ __forceinline__ uint32_t smem_u32(const void* p) {
    uint32_t a;
    asm("{ .reg .u64 t; cvta.to.shared.u64 t, %1; cvt.u32.u64 %0, t; }" : "=r"(a) : "l"(p));
    return a;
}
__device__ __forceinline__ void ldsm4(uint32_t* r, uint32_t addr) {
    asm volatile("ldmatrix.sync.aligned.m8n8.x4.shared.b16 {%0,%1,%2,%3}, [%4];"
        : "=r"(r[0]), "=r"(r[1]), "=r"(r[2]), "=r"(r[3]) : "r"(addr));
}
__device__ __forceinline__ void mma_f32acc(float* c, const uint32_t* a, const uint32_t* b) {
    asm volatile(
        "mma.sync.aligned.m16n8k16.row.col.f32.f16.f16.f32 "
        "{%0,%1,%2,%3}, {%4,%5,%6,%7}, {%8,%9}, {%0,%1,%2,%3};"
        : "+f"(c[0]), "+f"(c[1]), "+f"(c[2]), "+f"(c[3])
        : "r"(a[0]), "r"(a[1]), "r"(a[2]), "r"(a[3]), "r"(b[0]), "r"(b[1]));
}
__device__ __forceinline__ void cp_async16(uint32_t dst, const void* src, uint32_t sz) {
    asm volatile("cp.async.cg.shared.global [%0], [%1], 16, %2;"
        :: "r"(dst), "l"(src), "r"(sz) : "memory");
}
#define CP_COMMIT() asm volatile("cp.async.commit_group;" ::: "memory")
#define CP_WAIT(n)  asm volatile("cp.async.wait_group %0;" :: "n"(n) : "memory")

// ---------------- mega conversion kernel (fp32 -> fp16 hi only) --------
#define NB_V  (MV / 4)
#define NB_Q  (MQ / 4)
#define NB_WV 64
#define NB_WO 64
#define NB_WA 32
#define NB_WU 64
#define NB_TOT (NB_V + NB_Q + NB_WV + NB_WO + NB_WA + NB_WU + 1)

struct ConvArgs {
    const float *vlv, *query, *w_val, *w_off, *w_attn, *w_out, *b_off, *b_attn;
};

__global__ void __launch_bounds__(256) convert_all_kernel(ConvArgs a)
{
    const int blk = blockIdx.x;
    const int tid = threadIdx.x;

    const float* src;
    uint2 *hi;
    int rel;

    if (blk < NB_V) {
        src = a.vlv; hi = (uint2*)g_v_hi; rel = blk;
    } else if (blk < NB_V + NB_Q) {
        src = a.query; hi = (uint2*)g_q_hi; rel = blk - NB_V;
    } else if (blk < NB_V + NB_Q + NB_WV) {
        src = a.w_val; hi = (uint2*)g_w_hi; rel = blk - (NB_V + NB_Q);
    } else if (blk < NB_V + NB_Q + NB_WV + NB_WO) {
        src = a.w_off; hi = (uint2*)(g_w_hi + 65536);
        rel = blk - (NB_V + NB_Q + NB_WV);
    } else if (blk < NB_V + NB_Q + NB_WV + NB_WO + NB_WA) {
        src = a.w_attn; hi = (uint2*)(g_w_hi + 131072);
        rel = blk - (NB_V + NB_Q + NB_WV + NB_WO);
    } else if (blk < NB_V + NB_Q + NB_WV + NB_WO + NB_WA + NB_WU) {
        src = a.w_out; hi = (uint2*)(g_w_hi + 163840);
        rel = blk - (NB_V + NB_Q + NB_WV + NB_WO + NB_WA);
    } else {
        for (int i = tid; i < 384; i += 256)
            g_qb[i] = (i < 256) ? a.b_off[i] : a.b_attn[i - 256];
        return;
    }

    const int i = rel * 256 + tid;
    const float4 v = ((const float4*)src)[i];
    __half h0 = __float2half_rn(v.x), h1 = __float2half_rn(v.y);
    __half h2 = __float2half_rn(v.z), h3 = __float2half_rn(v.w);
    uint2 hp;
    hp.x = (uint32_t)__half_as_ushort(h0) | ((uint32_t)__half_as_ushort(h1) << 16);
    hp.y = (uint32_t)__half_as_ushort(h2) | ((uint32_t)__half_as_ushort(h3) << 16);
    hi[i] = hp;
}

// ============ HMMA GEMM: pure fp16, 256 thr, 64x32 warp tile, 2 CTAs/SM ============
// tile 128x128, K in 8 half-stages of 32. smem 32KB: A | B planes of 16KB.
// outHalf: epilogue writes __half instead of float.
struct GemmSeg {
    const __half *Ahi, *Bhi;
    const float* bias;
    void* C;
    int M, N, ntiles, tilesPerRow, outHalf;
};

__global__ void __launch_bounds__(256, 2) gemm_tc2_kernel(GemmSeg s0, GemmSeg s1)
{
    extern __shared__ char smraw[];
    char* sm = (char*)(((uintptr_t)smraw + 1023) & ~(uintptr_t)1023);
    const uint32_t su = smem_u32(sm);
    float* pbias = (float*)(sm + 32768);

    int t = blockIdx.x;
    const __half *Ahi, *Bhi;
    const float* bias;
    void* Cv;
    int M, N, tpr, outHalf;
    if (t < s0.ntiles) {
        Ahi = s0.Ahi; Bhi = s0.Bhi;
        bias = s0.bias; Cv = s0.C; M = s0.M; N = s0.N; tpr = s0.tilesPerRow; outHalf = s0.outHalf;
    } else {
        t -= s0.ntiles;
        Ahi = s1.Ahi; Bhi = s1.Bhi;
        bias = s1.bias; Cv = s1.C; M = s1.M; N = s1.N; tpr = s1.tilesPerRow; outHalf = s1.outHalf;
    }
    const int bm = (t / tpr) * 128;
    const int bn = (t % tpr) * 128;

    const int tid  = threadIdx.x;
    const int lane = tid & 31;
    const int warp = tid >> 5;
    const int wm = (warp >> 2) * 64;      // 2x4 layout: warp tile 64 rows x 32 cols
    const int wn = (warp & 3) * 32;

    if (tid < 128) pbias[tid] = bias[bn + tid];

    float acc[4][4][4];
#pragma unroll
    for (int i = 0; i < 4; i++)
#pragma unroll
        for (int j = 0; j < 4; j++)
#pragma unroll
            for (int k = 0; k < 4; k++) acc[i][j][k] = 0.f;

    const uint32_t mx = (uint32_t)((lane & 7) << 4);
    uint32_t aRow[4], bRow[2];
#pragma unroll
    for (int mi = 0; mi < 4; mi++)
        aRow[mi] = (uint32_t)((wm + mi * 16 + (lane & 15)) * 128);
    const uint32_t colA = (uint32_t)((lane >> 4) * 16);
#pragma unroll
    for (int nj2 = 0; nj2 < 2; nj2++)
        bRow[nj2] = (uint32_t)((wn + nj2 * 16 + (lane & 7) + ((lane >> 4) & 1) * 8) * 128);
    const uint32_t colB = (uint32_t)(((lane >> 3) & 1) * 16);

    // one K-32 half-stage into half (hs&1) of both planes; 256 threads, 4 cp.async each
    auto load_half = [&](int hs) {
        const int hb = (hs & 1) * 64;
        const int ksrc = hs * 64;
#pragma unroll
        for (int pl = 0; pl < 2; pl++) {
            const __half* gsrc = (pl == 0) ? Ahi : Bhi;
            const bool isA = (pl == 0);
            const uint32_t pbase = su + (uint32_t)pl * 16384u;
#pragma unroll
            for (int it = 0; it < 2; it++) {
                const int idx = it * 256 + tid;        // 0..511
                const int r = idx >> 2;
                const int c = idx & 3;
                const uint32_t doff = (uint32_t)(r * 128)
                    + (uint32_t)((hb + c * 16) ^ ((r & 7) << 4));
                const int grow = (isA ? bm : bn) + r;
                const uint32_t sz = (isA && grow >= M) ? 0u : 16u;
                const size_t soff = (size_t)grow * 512 + ksrc + c * 16;
                cp_async16(pbase + doff, (const char*)gsrc + soff, sz);
            }
        }
    };

    load_half(0); CP_COMMIT();
    load_half(1); CP_COMMIT();

    for (int hs = 0; hs < 8; hs++) {
        if (hs < 7) CP_WAIT(1); else CP_WAIT(0);
        __syncthreads();

        const uint32_t hb = (uint32_t)((hs & 1) * 64);
#pragma unroll
        for (int kk = 0; kk < 2; kk++) {
            uint32_t ah[4][4], bh[2][4];
            const uint32_t ca = (hb + (uint32_t)(kk * 32) + colA) ^ mx;
            const uint32_t cb = (hb + (uint32_t)(kk * 32) + colB) ^ mx;
#pragma unroll
            for (int mi = 0; mi < 4; mi++)
                ldsm4(ah[mi], su + aRow[mi] + ca);
#pragma unroll
            for (int nj2 = 0; nj2 < 2; nj2++)
                ldsm4(bh[nj2], su + 16384 + bRow[nj2] + cb);
#pragma unroll
            for (int mi = 0; mi < 4; mi++)
#pragma unroll
                for (int nj = 0; nj < 4; nj++)
                    mma_f32acc(acc[mi][nj], ah[mi], &bh[nj >> 1][(nj & 1) * 2]);
        }
        __syncthreads();
        if (hs < 6) { load_half(hs + 2); CP_COMMIT(); }
    }

    const int r0 = lane >> 2;
    const int c0 = (lane & 3) * 2;
#pragma unroll
    for (int mi = 0; mi < 4; mi++) {
        const int gm = bm + wm + mi * 16 + r0;
#pragma unroll
        for (int half = 0; half < 2; half++) {
            const int gmr = gm + half * 8;
            if (gmr < M) {
                if (outHalf) {
                    __half* op = (__half*)Cv + (size_t)gmr * N + bn;
#pragma unroll
                    for (int nj = 0; nj < 4; nj++) {
                        const int cl = wn + nj * 8 + c0;
                        *(__half2*)(op + cl) = __floats2half2_rn(
                            acc[mi][nj][half * 2 + 0] + pbias[cl],
                            acc[mi][nj][half * 2 + 1] + pbias[cl + 1]);
                    }
                } else {
                    float* op = (float*)Cv + (size_t)gmr * N + bn;
#pragma unroll
                    for (int nj = 0; nj < 4; nj++) {
                        const int cl = wn + nj * 8 + c0;
                        float2 o;
                        o.x = acc[mi][nj][half * 2 + 0] + pbias[cl];
                        o.y = acc[mi][nj][half * 2 + 1] + pbias[cl + 1];
                        *(float2*)(op + cl) = o;
                    }
                }
            }
        }
    }
}

// ---------------- sampling: softmax + fp16 quad-channel gather ----------
__global__ void __launch_bounds__(256) sample_kernel(
    const float* __restrict__ ref)
{
    constexpr int LH[4]  = {100, 50, 25, 13};
    constexpr int LW[4]  = {150, 75, 38, 19};
    constexpr int LST[4] = {0, 15000, 18750, 19700};

    const int warp = (blockIdx.x * blockDim.x + threadIdx.x) >> 5;
    const int lane = threadIdx.x & 31;
    if (warp >= BB * NQ * NHD) return;

    const int h  = warp % NHD;
    const int bq = warp / NHD;
    const int b  = bq / NQ;
    const int sl = (lane >> 2) & 3;

    const float* qrow = g_qout + (size_t)bq * 384;

    const float* logit = qrow + 256 + h * 16;
    float lg = (lane < 16) ? logit[lane] : -1e30f;
    float mxv = lg;
#pragma unroll
    for (int o = 8; o; o >>= 1) mxv = fmaxf(mxv, __shfl_xor_sync(0xffffffffu, mxv, o, 16));
    float ev = __expf(lg - mxv);
    float sum = ev;
#pragma unroll
    for (int o = 8; o; o >>= 1) sum += __shfl_xor_sync(0xffffffffu, sum, o, 16);
    const float aw = ev / sum;

    const float2 off2 = ((const float2*)(qrow + h * 32))[lane & 15];
    const float2 rxy  = ((const float2*)(ref + (size_t)bq * 8))[sl];
    const float fW = (float)LW[sl], fH = (float)LH[sl];
    const float x = (rxy.x + off2.x / fW) * fW - 0.5f;
    const float y = (rxy.y + off2.y / fH) * fH - 0.5f;
    const float x0f = floorf(x), y0f = floorf(y);
    const float wx1 = x - x0f, wy1 = y - y0f;
    const int pk = (((int)y0f) << 16) | (((int)x0f) & 0xffff);
    const float wy0a_o = (1.f - wy1) * aw;
    const float wy1a_o = wy1 * aw;

    const int grp  = lane >> 3;
    const int chan = (lane & 7) * 4;
    float a0 = 0.f, a1 = 0.f, a2 = 0.f, a3 = 0.f;

#pragma unroll
    for (int l = 0; l < 4; l++) {
        const int W = LW[l], H = LH[l];
        const __half* vbase = g_value_h
            + ((size_t)(b * S_TOT + LST[l]) * NHD + h) * DH + chan;
        const int src = l * 4 + grp;
        const int   bpk  = __shfl_sync(0xffffffffu, pk,     src);
        const float bwx  = __shfl_sync(0xffffffffu, wx1,    src);
        const float wy0a = __shfl_sync(0xffffffffu, wy0a_o, src);
        const float wy1a = __shfl_sync(0xffffffffu, wy1a_o, src);
        const int bix = (int)(short)(bpk & 0xffff);
        const int biy = bpk >> 16;
        const float wx0 = 1.f - bwx;
        const bool xi0 = (unsigned)bix < (unsigned)W;
        const bool xi1 = (unsigned)(bix + 1) < (unsigned)W;
        const bool yi0 = (unsigned)biy < (unsigned)H;
        const bool yi1 = (unsigned)(biy + 1) < (unsigned)H;
        const __half* pp0 = vbase + (ptrdiff_t)(biy * W + bix) * 256;
        if (yi0 && xi0) { const uint2 v = *(const uint2*)pp0;
            const float2 f01 = __half22float2(*(const __half2*)&v.x);
            const float2 f23 = __half22float2(*(const __half2*)&v.y);
            const float w = wx0 * wy0a;
            a0 = fmaf(w, f01.x, a0); a1 = fmaf(w, f01.y, a1);
            a2 = fmaf(w, f23.x, a2); a3 = fmaf(w, f23.y, a3); }
        if (yi0 && xi1) { const uint2 v = *(const uint2*)(pp0 + 256);
            const float2 f01 = __half22float2(*(const __half2*)&v.x);
            const float2 f23 = __half22float2(*(const __half2*)&v.y);
            const float w = bwx * wy0a;
            a0 = fmaf(w, f01.x, a0); a1 = fmaf(w, f01.y, a1);
            a2 = fmaf(w, f23.x, a2); a3 = fmaf(w, f23.y, a3); }
        if (yi1 && xi0) { const uint2 v = *(const uint2*)(pp0 + W * 256);
            const float2 f01 = __half22float2(*(const __half2*)&v.x);
            const float2 f23 = __half22float2(*(const __half2*)&v.y);
            const float w = wx0 * wy1a;
            a0 = fmaf(w, f01.x, a0); a1 = fmaf(w, f01.y, a1);
            a2 = fmaf(w, f23.x, a2); a3 = fmaf(w, f23.y, a3); }
        if (yi1 && xi1) { const uint2 v = *(const uint2*)(pp0 + W * 256 + 256);
            const float2 f01 = __half22float2(*(const __half2*)&v.x);
            const float2 f23 = __half22float2(*(const __half2*)&v.y);
            const float w = bwx * wy1a;
            a0 = fmaf(w, f01.x, a0); a1 = fmaf(w, f01.y, a1);
            a2 = fmaf(w, f23.x, a2); a3 = fmaf(w, f23.y, a3); }
    }
#pragma unroll
    for (int o = 8; o <= 16; o <<= 1) {
        a0 += __shfl_xor_sync(0xffffffffu, a0, o);
        a1 += __shfl_xor_sync(0xffffffffu, a1, o);
        a2 += __shfl_xor_sync(0xffffffffu, a2, o);
        a3 += __shfl_xor_sync(0xffffffffu, a3, o);
    }

    if (lane < 8) {
        __half h0 = __float2half_rn(a0), h1 = __float2half_rn(a1);
        __half h2 = __float2half_rn(a2), h3 = __float2half_rn(a3);
        uint2 hp;
        hp.x = (uint32_t)__half_as_ushort(h0) | ((uint32_t)__half_as_ushort(h1) << 16);
        hp.y = (uint32_t)__half_as_ushort(h2) | ((uint32_t)__half_as_ushort(h3) << 16);
        const size_t q2 = (size_t)(bq * NHD + h) * 8 + (lane & 7);
        ((uint2*)g_s_hi)[q2] = hp;
    }
}

// ---------------- launch ----------------
#define GEMM_SMEM_BYTES 34304

extern "C" void kernel_launch(void* const* d_in, const int* in_sizes, int n_in,
                              void* d_out, int out_size)
{
    (void)in_sizes; (void)n_in; (void)out_size;
    const float* query  = (const float*)d_in[0];
    const float* vlv    = (const float*)d_in[1];
    const float* refpts = (const float*)d_in[2];
    const float* W_off  = (const float*)d_in[4];
    const float* b_off  = (const float*)d_in[5];
    const float* W_attn = (const float*)d_in[6];
    const float* b_attn = (const float*)d_in[7];
    const float* W_val  = (const float*)d_in[8];
    const float* b_val  = (const float*)d_in[9];
    const float* W_out  = (const float*)d_in[10];
    const float* b_out  = (const float*)d_in[11];
    float* out = (float*)d_out;

    cudaFuncSetAttribute(gemm_tc2_kernel,
                         cudaFuncAttributeMaxDynamicSharedMemorySize, GEMM_SMEM_BYTES);

    float *p_qout, *p_qb;
    __half *p_valh, *p_vhi, *p_qhi, *p_shi, *p_whi;
    cudaGetSymbolAddress((void**)&p_valh,  g_value_h);
    cudaGetSymbolAddress((void**)&p_qout,  g_qout);
    cudaGetSymbolAddress((void**)&p_qb,    g_qb);
    cudaGetSymbolAddress((void**)&p_vhi,   g_v_hi);
    cudaGetSymbolAddress((void**)&p_qhi,   g_q_hi);
    cudaGetSymbolAddress((void**)&p_shi,   g_s_hi);
    cudaGetSymbolAddress((void**)&p_whi,   g_w_hi);

    __half *wv_hi = p_whi;
    __half *qw_hi = p_whi + 65536;
    __half *wu_hi = p_whi + 163840;

    {
        ConvArgs ca;
        ca.vlv = vlv; ca.query = query;
        ca.w_val = W_val; ca.w_off = W_off; ca.w_attn = W_attn; ca.w_out = W_out;
        ca.b_off = b_off; ca.b_attn = b_attn;
        convert_all_kernel<<<NB_TOT, 256>>>(ca);
    }

    {
        GemmSeg sv, sq;
        sv.Ahi = p_vhi; sv.Bhi = wv_hi;
        sv.bias = b_val; sv.C = p_valh; sv.M = MV; sv.N = 256;
        sv.tilesPerRow = 2; sv.ntiles = ((MV + 127) / 128) * 2; sv.outHalf = 1;
        sq.Ahi = p_qhi; sq.Bhi = qw_hi;
        sq.bias = p_qb; sq.C = p_qout; sq.M = MQ; sq.N = 384;
        sq.tilesPerRow = 3; sq.ntiles = (MQ / 128) * 3; sq.outHalf = 0;
        gemm_tc2_kernel<<<sv.ntiles + sq.ntiles, 256, GEMM_SMEM_BYTES>>>(sv, sq);
    }

    {
        const int nwarp = BB * NQ * NHD;
        sample_kernel<<<(nwarp * 32 + 255) / 256, 256>>>(refpts);
    }

    {
        GemmSeg so, dummy;
        so.Ahi = p_shi; so.Bhi = wu_hi;
        so.bias = b_out; so.C = out; so.M = MQ; so.N = 256;
        so.tilesPerRow = 2; so.ntiles = (MQ / 128) * 2; so.outHalf = 0;
        dummy = so; dummy.ntiles = 0;
        gemm_tc2_kernel<<<so.ntiles, 256, GEMM_SMEM_BYTES>>>(so, dummy);
    }
}